// round 1
// baseline (speedup 1.0000x reference)
#include <cuda_runtime.h>
#include <cuda_bf16.h>

// RotaryPositionEncoding3D: out[B,N,192,2] f32 from xyz[B,N,3] f32 and div_term[32] f32.
// Feature layout per point: f = 6*bin + 2*axis + dup, last dim (cos, sin).
// Each float4 of the output = (cos, sin, cos, sin) of a single angle
// ang = xyz[p, axis] * div_term[bin] with axis = j%3, bin = j/3, j = g%96.
// One thread computes one sincos and writes one coalesced 16B store.
// Kernel is HBM-store-bound (~403 MB written).

__global__ void __launch_bounds__(256)
rope3d_kernel(const float* __restrict__ xyz,
              const float* __restrict__ div_term,
              float4* __restrict__ out,
              int total_f4) {
    int g = blockIdx.x * blockDim.x + threadIdx.x;
    if (g >= total_f4) return;

    int p = g / 96;        // point index (b*N + n)
    int j = g - p * 96;    // pair index within point: j = 3*bin + axis
    int axis = j % 3;
    int bin  = j / 3;

    float x  = __ldg(&xyz[p * 3 + axis]);
    float dt = __ldg(&div_term[bin]);
    float ang = x * dt;

    float s, c;
    __sincosf(ang, &s, &c);   // |ang| <= 1, MUFU precision ample for rel_err < 1e-3

    out[g] = make_float4(c, s, c, s);
}

extern "C" void kernel_launch(void* const* d_in, const int* in_sizes, int n_in,
                              void* d_out, int out_size) {
    const float* xyz      = (const float*)d_in[0];
    const float* div_term = (const float*)d_in[1];
    float4* out = (float4*)d_out;

    int total_f4 = out_size / 4;           // 25,165,824 for B=4, N=65536
    int threads = 256;
    int blocks = (total_f4 + threads - 1) / threads;
    rope3d_kernel<<<blocks, threads>>>(xyz, div_term, out, total_f4);
}

// round 2
// speedup vs baseline: 1.5717x; 1.5717x over previous
#include <cuda_runtime.h>
#include <cuda_bf16.h>

// RotaryPositionEncoding3D: out[B,N,192,2] f32 from xyz[B,N,3] f32 and div_term[32] f32.
// Feature layout per point: f = 6*bin + 2*axis + dup, last dim (cos, sin).
// Each output float4 g = (cos, sin, cos, sin) of angle xyz[p, axis]*div_term[bin],
//   p = g/96, j = g%96, axis = j%3, bin = j/3.
//
// v2: 4 float4s per thread at stride-256 within a 1024-float4 block tile.
//  - each of the 4 warp stores is 512B contiguous (full 128B lines, no RFO)
//  - 4 independent LDG->MUFU->STG chains per thread -> 4x store MLP vs v1
//  - streaming stores (__stcs): output is write-once, keep L2 for xyz
// Total: 402.6 MB stored; latency-exposure bound in v1 (DRAM only 49.5% busy).

#define F4_PER_THREAD 4
#define THREADS 256
#define TILE (THREADS * F4_PER_THREAD)   // 1024 float4 per block

__global__ void __launch_bounds__(THREADS)
rope3d_kernel(const float* __restrict__ xyz,
              const float* __restrict__ div_term,
              float4* __restrict__ out,
              int total_f4) {
    const int base = blockIdx.x * TILE + threadIdx.x;

    float c[F4_PER_THREAD], s[F4_PER_THREAD];
    int   g[F4_PER_THREAD];

#pragma unroll
    for (int k = 0; k < F4_PER_THREAD; ++k) {
        g[k] = base + k * THREADS;
        int gi = g[k] < total_f4 ? g[k] : 0;   // clamp (tail-safe; exact fit in bench)
        int p  = gi / 96;                      // point index (b*N + n)
        int j  = gi - p * 96;                  // j = 3*bin + axis
        int bin  = j / 3;
        int axis = j - bin * 3;

        float x  = __ldg(&xyz[p * 3 + axis]);
        float dt = __ldg(&div_term[bin]);
        __sincosf(x * dt, &s[k], &c[k]);       // |ang| <= 1, MUFU precision ample
    }

#pragma unroll
    for (int k = 0; k < F4_PER_THREAD; ++k) {
        if (g[k] < total_f4)
            __stcs(&out[g[k]], make_float4(c[k], s[k], c[k], s[k]));
    }
}

extern "C" void kernel_launch(void* const* d_in, const int* in_sizes, int n_in,
                              void* d_out, int out_size) {
    const float* xyz      = (const float*)d_in[0];
    const float* div_term = (const float*)d_in[1];
    float4* out = (float4*)d_out;

    int total_f4 = out_size / 4;                     // 25,165,824 for B=4, N=65536
    int blocks = (total_f4 + TILE - 1) / TILE;       // 24,576 (exact fit)
    rope3d_kernel<<<blocks, THREADS>>>(xyz, div_term, out, total_f4);
}